// round 2
// baseline (speedup 1.0000x reference)
#include <cuda_runtime.h>

// ---------------------------------------------------------------------------
// GNNMLP: fused SAGE-pool(x2) + avg-pool + per-type MLP for 131072 6-node graphs.
// Strategy (round 0): persistent CTAs, weights resident in SMEM, one warp
// processes 2 graphs, all heavy math uses packed fp32x2 FMA (fma.rn.f32x2,
// Blackwell-only, 2x FLOP per issue vs scalar FFMA).
// ---------------------------------------------------------------------------

#define G_TOT   131072
#define THREADS 384
#define WARPS   12
#define GPC     (WARPS * 2)   // groups per CTA per iteration

typedef unsigned long long ull;

// ---- packed f32x2 helpers (sm_103a) ---------------------------------------
__device__ __forceinline__ ull pk2(float x, float y) {
    ull r; asm("mov.b64 %0, {%1,%2};" : "=l"(r) : "f"(x), "f"(y)); return r;
}
__device__ __forceinline__ ull pk1(float x) { return pk2(x, x); }
__device__ __forceinline__ float2 upk(ull v) {
    float2 r; asm("mov.b64 {%0,%1}, %2;" : "=f"(r.x), "=f"(r.y) : "l"(v)); return r;
}
__device__ __forceinline__ ull f2fma(ull a, ull b, ull c) {
    ull d; asm("fma.rn.f32x2 %0, %1, %2, %3;" : "=l"(d) : "l"(a), "l"(b), "l"(c));
    return d;
}

// ---- SMEM layout (in floats) ----------------------------------------------
#define OFF_WP1  0
#define OFF_WS1  4096
#define OFF_WP2  8192
#define OFF_WS2  12288
#define OFF_MW1  16384
#define OFF_MW2  24576
#define OFF_MW3  32768
#define OFF_BIAS 40960
//   BIAS region: +0 bp1(64) +64 b1(64) +128 bp2(64) +192 b2(64)
//                +256 Mb1(128) +384 Mb2(128) +512 Mb3(128) +640 MW4(256) +896 Mb4(4)
#define OFF_WS_  41984
#define WARP_WS  1280          // OBS 768 | NB 128 | RES 128 | XA 128 | XB 128
#define SMEM_FLOATS (OFF_WS_ + WARPS * WARP_WS)   // 57344
#define SMEM_BYTES  (SMEM_FLOATS * 4)             // 229376 < 232448

struct Params {
    const float *obs, *Wp1, *bp1, *Ws1, *Wn1, *b1;
    const float *Wp2, *bp2, *Ws2, *Wn2, *b2;
    const float *MW1, *Mb1, *MW2, *Mb2, *MW3, *Mb3, *MW4, *Mb4;
    float *out;
};

extern __shared__ float smem[];

__device__ __forceinline__ void cp4(float* dst, const float* src, int n) {
    for (int i = threadIdx.x; i < (n >> 2); i += THREADS)
        ((float4*)dst)[i] = ((const float4*)src)[i];
}

// ---- one SAGE-pool conv on 12 rows (2 groups x 6 agents) -------------------
// rows: [12][64] in SMEM. Lane owns output cols {2*lane, 2*lane+1}.
// FIRST: apply tanh and store h back to rows.  else: store mean-pooled res.
template<bool FIRST>
__device__ __forceinline__ void sage(float* rows, float* nbuf, float* resbuf,
                                     const float* sWp, const float* sWs,
                                     const float* __restrict__ gWn,
                                     const float* bp, const float* bb, int lane)
{
    ull aP[12], aS[12];
    ull bpv = *(const ull*)(bp + 2 * lane);
    #pragma unroll
    for (int r = 0; r < 12; r++) { aP[r] = bpv; aS[r] = 0ull; }

    const ull* wp  = (const ull*)sWp + lane;   // row k lives at +k*32
    const ull* wss = (const ull*)sWs + lane;

    #pragma unroll 4
    for (int k = 0; k < 64; k += 2) {
        ull w0p = wp[k * 32],      w0s = wss[k * 32];
        ull w1p = wp[k * 32 + 32], w1s = wss[k * 32 + 32];
        #pragma unroll
        for (int r = 0; r < 12; r++) {
            float2 ov = *(const float2*)(rows + r * 64 + k);  // warp-broadcast LDS.64
            ull b0 = pk1(ov.x), b1 = pk1(ov.y);
            aP[r] = f2fma(b0, w0p, aP[r]);
            aS[r] = f2fma(b0, w0s, aS[r]);
            aP[r] = f2fma(b1, w1p, aP[r]);
            aS[r] = f2fma(b1, w1s, aS[r]);
        }
    }

    // neigh = max over 6 agents of relu(p)  (relu folded into max with 0 init)
    #pragma unroll
    for (int g = 0; g < 2; g++) {
        float mx = 0.f, my = 0.f;
        #pragma unroll
        for (int r = 0; r < 6; r++) {
            float2 p = upk(aP[g * 6 + r]);
            mx = fmaxf(mx, p.x); my = fmaxf(my, p.y);
        }
        *(float2*)(nbuf + g * 64 + 2 * lane) = make_float2(mx, my);
    }
    __syncwarp();

    // nn = neigh @ Wn   (Wn streamed from global; L1-resident, light traffic)
    ull nn0 = 0ull, nn1 = 0ull;
    const ull* wn = (const ull*)gWn + lane;
    #pragma unroll 4
    for (int k = 0; k < 64; k++) {
        ull w = wn[k * 32];
        nn0 = f2fma(pk1(nbuf[k]),      w, nn0);
        nn1 = f2fma(pk1(nbuf[64 + k]), w, nn1);
    }
    float2 bbv = *(const float2*)(bb + 2 * lane);
    float2 n0 = upk(nn0), n1 = upk(nn1);
    n0.x += bbv.x; n0.y += bbv.y;
    n1.x += bbv.x; n1.y += bbv.y;

    if (FIRST) {
        #pragma unroll
        for (int r = 0; r < 12; r++) {
            float2 s = upk(aS[r]);
            float2 nb = (r < 6) ? n0 : n1;
            s.x = tanhf(s.x + nb.x);
            s.y = tanhf(s.y + nb.y);
            *(float2*)(rows + r * 64 + 2 * lane) = s;
        }
        __syncwarp();
    } else {
        #pragma unroll
        for (int g = 0; g < 2; g++) {
            float sx = 0.f, sy = 0.f;
            #pragma unroll
            for (int r = 0; r < 6; r++) {
                float2 s = upk(aS[g * 6 + r]); sx += s.x; sy += s.y;
            }
            float2 nb = g ? n1 : n0;
            sx = sx * (1.f / 6.f) + nb.x;
            sy = sy * (1.f / 6.f) + nb.y;
            *(float2*)(resbuf + g * 64 + 2 * lane) = make_float2(sx, sy);
        }
        __syncwarp();
    }
}

// ---- one MLP layer for both groups (in[0:64], in[64:128]) ------------------
__device__ __forceinline__ void mlp_layer(const float* in, float* out,
                                          const float* W, const float* b, int lane)
{
    ull a0, a1;
    a0 = a1 = *(const ull*)(b + 2 * lane);
    const ull* wB = (const ull*)W + lane;
    #pragma unroll 4
    for (int k = 0; k < 64; k++) {
        ull w = wB[k * 32];
        a0 = f2fma(pk1(in[k]),      w, a0);
        a1 = f2fma(pk1(in[64 + k]), w, a1);
    }
    float2 x0 = upk(a0), x1 = upk(a1);
    *(float2*)(out + 2 * lane)      = make_float2(fmaxf(x0.x, 0.f), fmaxf(x0.y, 0.f));
    *(float2*)(out + 64 + 2 * lane) = make_float2(fmaxf(x1.x, 0.f), fmaxf(x1.y, 0.f));
    __syncwarp();
}

__global__ void __launch_bounds__(THREADS, 1) gnn_kernel(Params P)
{
    // weights -> SMEM once per persistent CTA
    cp4(smem + OFF_WP1, P.Wp1, 4096);
    cp4(smem + OFF_WS1, P.Ws1, 4096);
    cp4(smem + OFF_WP2, P.Wp2, 4096);
    cp4(smem + OFF_WS2, P.Ws2, 4096);
    cp4(smem + OFF_MW1, P.MW1, 8192);
    cp4(smem + OFF_MW2, P.MW2, 8192);
    cp4(smem + OFF_MW3, P.MW3, 8192);
    cp4(smem + OFF_BIAS +   0, P.bp1, 64);
    cp4(smem + OFF_BIAS +  64, P.b1,  64);
    cp4(smem + OFF_BIAS + 128, P.bp2, 64);
    cp4(smem + OFF_BIAS + 192, P.b2,  64);
    cp4(smem + OFF_BIAS + 256, P.Mb1, 128);
    cp4(smem + OFF_BIAS + 384, P.Mb2, 128);
    cp4(smem + OFF_BIAS + 512, P.Mb3, 128);
    cp4(smem + OFF_BIAS + 640, P.MW4, 256);
    cp4(smem + OFF_BIAS + 896, P.Mb4, 4);
    __syncthreads();

    const int lane = threadIdx.x & 31;
    const int warp = threadIdx.x >> 5;
    float* ws  = smem + OFF_WS_ + warp * WARP_WS;
    float* OBS = ws;            // [12][64]
    float* NB  = ws + 768;      // neigh  [2][64]
    float* RES = ws + 896;      // pooled [2][64]
    float* XA  = ws + 1024;
    float* XB  = ws + 1152;
    const float* BIAS = smem + OFF_BIAS;

    for (int base = blockIdx.x * GPC; base < G_TOT; base += gridDim.x * GPC) {
        const int g0 = base + warp * 2;
        const int g1 = g0 + 1;
        const bool v0 = g0 < G_TOT, v1 = g1 < G_TOT;

        __syncwarp();
        {   // stage obs for both groups (zero-fill invalid to avoid NaN garbage)
            const float4* s0 = (const float4*)(P.obs + (size_t)g0 * 384);
            const float4* s1 = (const float4*)(P.obs + (size_t)g1 * 384);
            float4* d = (float4*)OBS;
            const float4 z = make_float4(0.f, 0.f, 0.f, 0.f);
            #pragma unroll
            for (int i = 0; i < 3; i++) {
                int j = lane + 32 * i;
                d[j]      = v0 ? s0[j] : z;
                d[96 + j] = v1 ? s1[j] : z;
            }
        }
        __syncwarp();

        sage<true >(OBS, NB, RES, smem + OFF_WP1, smem + OFF_WS1, P.Wn1,
                    BIAS + 0,   BIAS + 64,  lane);
        sage<false>(OBS, NB, RES, smem + OFF_WP2, smem + OFF_WS2, P.Wn2,
                    BIAS + 128, BIAS + 192, lane);

        float o[2][2][2];
        #pragma unroll
        for (int t = 0; t < 2; t++) {
            mlp_layer(RES, XA, smem + OFF_MW1 + t * 4096, BIAS + 256 + t * 64, lane);
            mlp_layer(XA,  XB, smem + OFF_MW2 + t * 4096, BIAS + 384 + t * 64, lane);
            mlp_layer(XB,  XA, smem + OFF_MW3 + t * 4096, BIAS + 512 + t * 64, lane);

            // final [64]->2 head via warp reduction
            const float* w4 = BIAS + 640 + t * 128;    // MW4[t][k][o]
            float w00 = w4[4 * lane], w01 = w4[4 * lane + 1];
            float w10 = w4[4 * lane + 2], w11 = w4[4 * lane + 3];
            float x0 = XA[2 * lane], x1 = XA[2 * lane + 1];
            float y0 = XA[64 + 2 * lane], y1 = XA[64 + 2 * lane + 1];
            float s00 = x0 * w00 + x1 * w10;
            float s01 = x0 * w01 + x1 * w11;
            float s10 = y0 * w00 + y1 * w10;
            float s11 = y0 * w01 + y1 * w11;
            #pragma unroll
            for (int off = 16; off; off >>= 1) {
                s00 += __shfl_xor_sync(0xffffffffu, s00, off);
                s01 += __shfl_xor_sync(0xffffffffu, s01, off);
                s10 += __shfl_xor_sync(0xffffffffu, s10, off);
                s11 += __shfl_xor_sync(0xffffffffu, s11, off);
            }
            o[t][0][0] = tanhf(s00 + BIAS[896 + t * 2 + 0]);
            o[t][0][1] = tanhf(s01 + BIAS[896 + t * 2 + 1]);
            o[t][1][0] = tanhf(s10 + BIAS[896 + t * 2 + 0]);
            o[t][1][1] = tanhf(s11 + BIAS[896 + t * 2 + 1]);
            __syncwarp();
        }

        // out[g][a][:] = a<5 ? type0 : type1  -> 12 floats = [A,B]*5 + [C,D]
        if (lane < 2) {
            const int  g  = (lane == 0) ? g0 : g1;
            const bool gv = (lane == 0) ? v0 : v1;
            if (gv) {
                float A = o[0][lane][0], B = o[0][lane][1];
                float C = o[1][lane][0], D = o[1][lane][1];
                float4* dst = (float4*)(P.out + (size_t)g * 12);
                dst[0] = make_float4(A, B, A, B);
                dst[1] = make_float4(A, B, A, B);
                dst[2] = make_float4(A, B, C, D);
            }
        }
    }
}

extern "C" void kernel_launch(void* const* d_in, const int* in_sizes, int n_in,
                              void* d_out, int out_size)
{
    (void)in_sizes; (void)n_in; (void)out_size;
    Params P;
    P.obs = (const float*)d_in[0];
    P.Wp1 = (const float*)d_in[1];  P.bp1 = (const float*)d_in[2];
    P.Ws1 = (const float*)d_in[3];  P.Wn1 = (const float*)d_in[4];
    P.b1  = (const float*)d_in[5];
    P.Wp2 = (const float*)d_in[6];  P.bp2 = (const float*)d_in[7];
    P.Ws2 = (const float*)d_in[8];  P.Wn2 = (const float*)d_in[9];
    P.b2  = (const float*)d_in[10];
    P.MW1 = (const float*)d_in[11]; P.Mb1 = (const float*)d_in[12];
    P.MW2 = (const float*)d_in[13]; P.Mb2 = (const float*)d_in[14];
    P.MW3 = (const float*)d_in[15]; P.Mb3 = (const float*)d_in[16];
    P.MW4 = (const float*)d_in[17]; P.Mb4 = (const float*)d_in[18];
    P.out = (float*)d_out;

    int dev = 0, nsm = 148;
    cudaGetDevice(&dev);
    cudaDeviceGetAttribute(&nsm, cudaDevAttrMultiProcessorCount, dev);
    cudaFuncSetAttribute(gnn_kernel, cudaFuncAttributeMaxDynamicSharedMemorySize,
                         SMEM_BYTES);
    gnn_kernel<<<nsm, THREADS, SMEM_BYTES>>>(P);
}

// round 3
// speedup vs baseline: 1.0511x; 1.0511x over previous
#include <cuda_runtime.h>

// ---------------------------------------------------------------------------
// GNNMLP: fused SAGE-pool(x2) + avg-pool + per-type MLP for 131072 6-node graphs.
// Strategy (round 0): persistent CTAs, weights resident in SMEM, one warp
// processes 2 graphs, all heavy math uses packed fp32x2 FMA (fma.rn.f32x2,
// Blackwell-only, 2x FLOP per issue vs scalar FFMA).
// ---------------------------------------------------------------------------

#define G_TOT   131072
#define THREADS 384
#define WARPS   12
#define GPC     (WARPS * 2)   // groups per CTA per iteration

typedef unsigned long long ull;

// ---- packed f32x2 helpers (sm_103a) ---------------------------------------
__device__ __forceinline__ ull pk2(float x, float y) {
    ull r; asm("mov.b64 %0, {%1,%2};" : "=l"(r) : "f"(x), "f"(y)); return r;
}
__device__ __forceinline__ ull pk1(float x) { return pk2(x, x); }
__device__ __forceinline__ float2 upk(ull v) {
    float2 r; asm("mov.b64 {%0,%1}, %2;" : "=f"(r.x), "=f"(r.y) : "l"(v)); return r;
}
__device__ __forceinline__ ull f2fma(ull a, ull b, ull c) {
    ull d; asm("fma.rn.f32x2 %0, %1, %2, %3;" : "=l"(d) : "l"(a), "l"(b), "l"(c));
    return d;
}

// ---- SMEM layout (in floats) ----------------------------------------------
#define OFF_WP1  0
#define OFF_WS1  4096
#define OFF_WP2  8192
#define OFF_WS2  12288
#define OFF_MW1  16384
#define OFF_MW2  24576
#define OFF_MW3  32768
#define OFF_BIAS 40960
//   BIAS region: +0 bp1(64) +64 b1(64) +128 bp2(64) +192 b2(64)
//                +256 Mb1(128) +384 Mb2(128) +512 Mb3(128) +640 MW4(256) +896 Mb4(4)
#define OFF_WS_  41984
#define WARP_WS  1280          // OBS 768 | NB 128 | RES 128 | XA 128 | XB 128
#define SMEM_FLOATS (OFF_WS_ + WARPS * WARP_WS)   // 57344
#define SMEM_BYTES  (SMEM_FLOATS * 4)             // 229376 < 232448

struct Params {
    const float *obs, *Wp1, *bp1, *Ws1, *Wn1, *b1;
    const float *Wp2, *bp2, *Ws2, *Wn2, *b2;
    const float *MW1, *Mb1, *MW2, *Mb2, *MW3, *Mb3, *MW4, *Mb4;
    float *out;
};

extern __shared__ float smem[];

__device__ __forceinline__ void cp4(float* dst, const float* src, int n) {
    for (int i = threadIdx.x; i < (n >> 2); i += THREADS)
        ((float4*)dst)[i] = ((const float4*)src)[i];
}

// ---- one SAGE-pool conv on 12 rows (2 groups x 6 agents) -------------------
// rows: [12][64] in SMEM. Lane owns output cols {2*lane, 2*lane+1}.
// FIRST: apply tanh and store h back to rows.  else: store mean-pooled res.
template<bool FIRST>
__device__ __forceinline__ void sage(float* rows, float* nbuf, float* resbuf,
                                     const float* sWp, const float* sWs,
                                     const float* __restrict__ gWn,
                                     const float* bp, const float* bb, int lane)
{
    ull aP[12], aS[12];
    ull bpv = *(const ull*)(bp + 2 * lane);
    #pragma unroll
    for (int r = 0; r < 12; r++) { aP[r] = bpv; aS[r] = 0ull; }

    const ull* wp  = (const ull*)sWp + lane;   // row k lives at +k*32
    const ull* wss = (const ull*)sWs + lane;

    #pragma unroll 4
    for (int k = 0; k < 64; k += 2) {
        ull w0p = wp[k * 32],      w0s = wss[k * 32];
        ull w1p = wp[k * 32 + 32], w1s = wss[k * 32 + 32];
        #pragma unroll
        for (int r = 0; r < 12; r++) {
            float2 ov = *(const float2*)(rows + r * 64 + k);  // warp-broadcast LDS.64
            ull b0 = pk1(ov.x), b1 = pk1(ov.y);
            aP[r] = f2fma(b0, w0p, aP[r]);
            aS[r] = f2fma(b0, w0s, aS[r]);
            aP[r] = f2fma(b1, w1p, aP[r]);
            aS[r] = f2fma(b1, w1s, aS[r]);
        }
    }

    // neigh = max over 6 agents of relu(p)  (relu folded into max with 0 init)
    #pragma unroll
    for (int g = 0; g < 2; g++) {
        float mx = 0.f, my = 0.f;
        #pragma unroll
        for (int r = 0; r < 6; r++) {
            float2 p = upk(aP[g * 6 + r]);
            mx = fmaxf(mx, p.x); my = fmaxf(my, p.y);
        }
        *(float2*)(nbuf + g * 64 + 2 * lane) = make_float2(mx, my);
    }
    __syncwarp();

    // nn = neigh @ Wn   (Wn streamed from global; L1-resident, light traffic)
    ull nn0 = 0ull, nn1 = 0ull;
    const ull* wn = (const ull*)gWn + lane;
    #pragma unroll 4
    for (int k = 0; k < 64; k++) {
        ull w = wn[k * 32];
        nn0 = f2fma(pk1(nbuf[k]),      w, nn0);
        nn1 = f2fma(pk1(nbuf[64 + k]), w, nn1);
    }
    float2 bbv = *(const float2*)(bb + 2 * lane);
    float2 n0 = upk(nn0), n1 = upk(nn1);
    n0.x += bbv.x; n0.y += bbv.y;
    n1.x += bbv.x; n1.y += bbv.y;

    if (FIRST) {
        #pragma unroll
        for (int r = 0; r < 12; r++) {
            float2 s = upk(aS[r]);
            float2 nb = (r < 6) ? n0 : n1;
            s.x = tanhf(s.x + nb.x);
            s.y = tanhf(s.y + nb.y);
            *(float2*)(rows + r * 64 + 2 * lane) = s;
        }
        __syncwarp();
    } else {
        #pragma unroll
        for (int g = 0; g < 2; g++) {
            float sx = 0.f, sy = 0.f;
            #pragma unroll
            for (int r = 0; r < 6; r++) {
                float2 s = upk(aS[g * 6 + r]); sx += s.x; sy += s.y;
            }
            float2 nb = g ? n1 : n0;
            sx = sx * (1.f / 6.f) + nb.x;
            sy = sy * (1.f / 6.f) + nb.y;
            *(float2*)(resbuf + g * 64 + 2 * lane) = make_float2(sx, sy);
        }
        __syncwarp();
    }
}

// ---- one MLP layer for both groups (in[0:64], in[64:128]) ------------------
__device__ __forceinline__ void mlp_layer(const float* in, float* out,
                                          const float* W, const float* b, int lane)
{
    ull a0, a1;
    a0 = a1 = *(const ull*)(b + 2 * lane);
    const ull* wB = (const ull*)W + lane;
    #pragma unroll 4
    for (int k = 0; k < 64; k++) {
        ull w = wB[k * 32];
        a0 = f2fma(pk1(in[k]),      w, a0);
        a1 = f2fma(pk1(in[64 + k]), w, a1);
    }
    float2 x0 = upk(a0), x1 = upk(a1);
    *(float2*)(out + 2 * lane)      = make_float2(fmaxf(x0.x, 0.f), fmaxf(x0.y, 0.f));
    *(float2*)(out + 64 + 2 * lane) = make_float2(fmaxf(x1.x, 0.f), fmaxf(x1.y, 0.f));
    __syncwarp();
}

__global__ void __launch_bounds__(THREADS, 1) gnn_kernel(Params P)
{
    // weights -> SMEM once per persistent CTA
    cp4(smem + OFF_WP1, P.Wp1, 4096);
    cp4(smem + OFF_WS1, P.Ws1, 4096);
    cp4(smem + OFF_WP2, P.Wp2, 4096);
    cp4(smem + OFF_WS2, P.Ws2, 4096);
    cp4(smem + OFF_MW1, P.MW1, 8192);
    cp4(smem + OFF_MW2, P.MW2, 8192);
    cp4(smem + OFF_MW3, P.MW3, 8192);
    cp4(smem + OFF_BIAS +   0, P.bp1, 64);
    cp4(smem + OFF_BIAS +  64, P.b1,  64);
    cp4(smem + OFF_BIAS + 128, P.bp2, 64);
    cp4(smem + OFF_BIAS + 192, P.b2,  64);
    cp4(smem + OFF_BIAS + 256, P.Mb1, 128);
    cp4(smem + OFF_BIAS + 384, P.Mb2, 128);
    cp4(smem + OFF_BIAS + 512, P.Mb3, 128);
    cp4(smem + OFF_BIAS + 640, P.MW4, 256);
    cp4(smem + OFF_BIAS + 896, P.Mb4, 4);
    __syncthreads();

    const int lane = threadIdx.x & 31;
    const int warp = threadIdx.x >> 5;
    float* ws  = smem + OFF_WS_ + warp * WARP_WS;
    float* OBS = ws;            // [12][64]
    float* NB  = ws + 768;      // neigh  [2][64]
    float* RES = ws + 896;      // pooled [2][64]
    float* XA  = ws + 1024;
    float* XB  = ws + 1152;
    const float* BIAS = smem + OFF_BIAS;

    for (int base = blockIdx.x * GPC; base < G_TOT; base += gridDim.x * GPC) {
        const int g0 = base + warp * 2;
        const int g1 = g0 + 1;
        const bool v0 = g0 < G_TOT, v1 = g1 < G_TOT;

        __syncwarp();
        {   // stage obs for both groups (zero-fill invalid to avoid NaN garbage)
            const float4* s0 = (const float4*)(P.obs + (size_t)g0 * 384);
            const float4* s1 = (const float4*)(P.obs + (size_t)g1 * 384);
            float4* d = (float4*)OBS;
            const float4 z = make_float4(0.f, 0.f, 0.f, 0.f);
            #pragma unroll
            for (int i = 0; i < 3; i++) {
                int j = lane + 32 * i;
                d[j]      = v0 ? s0[j] : z;
                d[96 + j] = v1 ? s1[j] : z;
            }
        }
        __syncwarp();

        sage<true >(OBS, NB, RES, smem + OFF_WP1, smem + OFF_WS1, P.Wn1,
                    BIAS + 0,   BIAS + 64,  lane);
        sage<false>(OBS, NB, RES, smem + OFF_WP2, smem + OFF_WS2, P.Wn2,
                    BIAS + 128, BIAS + 192, lane);

        float o[2][2][2];
        #pragma unroll
        for (int t = 0; t < 2; t++) {
            mlp_layer(RES, XA, smem + OFF_MW1 + t * 4096, BIAS + 256 + t * 64, lane);
            mlp_layer(XA,  XB, smem + OFF_MW2 + t * 4096, BIAS + 384 + t * 64, lane);
            mlp_layer(XB,  XA, smem + OFF_MW3 + t * 4096, BIAS + 512 + t * 64, lane);

            // final [64]->2 head via warp reduction
            const float* w4 = BIAS + 640 + t * 128;    // MW4[t][k][o]
            float w00 = w4[4 * lane], w01 = w4[4 * lane + 1];
            float w10 = w4[4 * lane + 2], w11 = w4[4 * lane + 3];
            float x0 = XA[2 * lane], x1 = XA[2 * lane + 1];
            float y0 = XA[64 + 2 * lane], y1 = XA[64 + 2 * lane + 1];
            float s00 = x0 * w00 + x1 * w10;
            float s01 = x0 * w01 + x1 * w11;
            float s10 = y0 * w00 + y1 * w10;
            float s11 = y0 * w01 + y1 * w11;
            #pragma unroll
            for (int off = 16; off; off >>= 1) {
                s00 += __shfl_xor_sync(0xffffffffu, s00, off);
                s01 += __shfl_xor_sync(0xffffffffu, s01, off);
                s10 += __shfl_xor_sync(0xffffffffu, s10, off);
                s11 += __shfl_xor_sync(0xffffffffu, s11, off);
            }
            o[t][0][0] = tanhf(s00 + BIAS[896 + t * 2 + 0]);
            o[t][0][1] = tanhf(s01 + BIAS[896 + t * 2 + 1]);
            o[t][1][0] = tanhf(s10 + BIAS[896 + t * 2 + 0]);
            o[t][1][1] = tanhf(s11 + BIAS[896 + t * 2 + 1]);
            __syncwarp();
        }

        // out[g][a][:] = a<5 ? type0 : type1  -> 12 floats = [A,B]*5 + [C,D]
        if (lane < 2) {
            const int  g  = (lane == 0) ? g0 : g1;
            const bool gv = (lane == 0) ? v0 : v1;
            if (gv) {
                float A = o[0][lane][0], B = o[0][lane][1];
                float C = o[1][lane][0], D = o[1][lane][1];
                float4* dst = (float4*)(P.out + (size_t)g * 12);
                dst[0] = make_float4(A, B, A, B);
                dst[1] = make_float4(A, B, A, B);
                dst[2] = make_float4(A, B, C, D);
            }
        }
    }
}

extern "C" void kernel_launch(void* const* d_in, const int* in_sizes, int n_in,
                              void* d_out, int out_size)
{
    (void)in_sizes; (void)n_in; (void)out_size;
    Params P;
    P.obs = (const float*)d_in[0];
    P.Wp1 = (const float*)d_in[1];  P.bp1 = (const float*)d_in[2];
    P.Ws1 = (const float*)d_in[3];  P.Wn1 = (const float*)d_in[4];
    P.b1  = (const float*)d_in[5];
    P.Wp2 = (const float*)d_in[6];  P.bp2 = (const float*)d_in[7];
    P.Ws2 = (const float*)d_in[8];  P.Wn2 = (const float*)d_in[9];
    P.b2  = (const float*)d_in[10];
    P.MW1 = (const float*)d_in[11]; P.Mb1 = (const float*)d_in[12];
    P.MW2 = (const float*)d_in[13]; P.Mb2 = (const float*)d_in[14];
    P.MW3 = (const float*)d_in[15]; P.Mb3 = (const float*)d_in[16];
    P.MW4 = (const float*)d_in[17]; P.Mb4 = (const float*)d_in[18];
    P.out = (float*)d_out;

    int dev = 0, nsm = 148;
    cudaGetDevice(&dev);
    cudaDeviceGetAttribute(&nsm, cudaDevAttrMultiProcessorCount, dev);
    cudaFuncSetAttribute(gnn_kernel, cudaFuncAttributeMaxDynamicSharedMemorySize,
                         SMEM_BYTES);
    gnn_kernel<<<nsm, THREADS, SMEM_BYTES>>>(P);
}